// round 11
// baseline (speedup 1.0000x reference)
#include <cuda_runtime.h>
#include <cuda_bf16.h>
#include <cuda_fp16.h>
#include <math.h>
#include <stdint.h>

// ---------------------------------------------------------------------------
// WindowedAttention on GB300 (sm_103a chip; ptxas target is base sm_103 so
// tcgen05 unavailable — warp-level mma.sync tensor cores).
// R10: GEMMs use 64x64 warp tiles (BM=128, BN=256) to halve the LDSM/MMA
//      byte ratio (smem crossbar was binding at 64x32). Stage 1 plain fp16,
//      stage 3 fp16 2-term split. Attention all-fp16 (R9 design).
// ---------------------------------------------------------------------------

#define C_DIM    768
#define QKV_DIM  2304
#define B_SZ     8
#define H_IMG    80
#define W_IMG    80
#define NTOK     (H_IMG * W_IMG)     // 6400
#define WIN      14
#define NW_WIN   6
#define LWIN     36
#define NWTOK    (WIN * WIN)         // 196
#define NHEADS   12
#define HDIM     64
#define MTOT     (B_SZ * NTOK)       // 51200

// ---------------- scratch (__device__ globals: allocation-free rule) -------
__device__ __half  g_qkvh[(size_t)MTOT * QKV_DIM];     // fp16 qkv
__device__ __half  g_xhi[(size_t)MTOT * C_DIM];
__device__ __half  g_wqkv_hi[(size_t)QKV_DIM * C_DIM]; // [N,K] K-major
__device__ __half  g_wproj_hi[(size_t)C_DIM * C_DIM];  // [N,K] K-major
__device__ __half  g_atthi[(size_t)MTOT * C_DIM];
__device__ __half  g_attlo[(size_t)MTOT * C_DIM];

extern __shared__ char smem_raw[];

// ---------------------------- PTX helpers ----------------------------------
__device__ __forceinline__ uint32_t smem_u32(const void* p) {
    uint32_t a;
    asm("{ .reg .u64 t; cvta.to.shared.u64 t, %1; cvt.u32.u64 %0, t; }"
        : "=r"(a) : "l"(p));
    return a;
}
__device__ __forceinline__ void cp16(uint32_t saddr, const void* g) {
    asm volatile("cp.async.cg.shared.global [%0], [%1], 16;" :: "r"(saddr), "l"(g));
}
__device__ __forceinline__ void cp_commit() { asm volatile("cp.async.commit_group;" ::: "memory"); }
template <int N> __device__ __forceinline__ void cp_wait() {
    asm volatile("cp.async.wait_group %0;" :: "n"(N) : "memory");
}
__device__ __forceinline__ void ldm_x4(uint32_t* r, uint32_t addr) {
    asm volatile("ldmatrix.sync.aligned.m8n8.x4.shared.b16 {%0,%1,%2,%3}, [%4];"
        : "=r"(r[0]), "=r"(r[1]), "=r"(r[2]), "=r"(r[3]) : "r"(addr));
}
__device__ __forceinline__ void ldm_x4_t(uint32_t* r, uint32_t addr) {
    asm volatile("ldmatrix.sync.aligned.m8n8.x4.trans.shared.b16 {%0,%1,%2,%3}, [%4];"
        : "=r"(r[0]), "=r"(r[1]), "=r"(r[2]), "=r"(r[3]) : "r"(addr));
}
// fp16 MMA, fp32 accum
__device__ __forceinline__ void mma16816h(float* d, const uint32_t* a, const uint32_t* b) {
    asm volatile(
        "mma.sync.aligned.m16n8k16.row.col.f32.f16.f16.f32 "
        "{%0,%1,%2,%3}, {%4,%5,%6,%7}, {%8,%9}, {%0,%1,%2,%3};"
        : "+f"(d[0]), "+f"(d[1]), "+f"(d[2]), "+f"(d[3])
        : "r"(a[0]), "r"(a[1]), "r"(a[2]), "r"(a[3]), "r"(b[0]), "r"(b[1]));
}
__device__ __forceinline__ uint32_t pack_f16(float lo, float hi) {
    __half2 h = __floats2half2_rn(lo, hi);
    return *(uint32_t*)&h;
}

// ---------------------------------------------------------------------------
// Warp-MMA GEMM: C[M,N] = A[M,768] @ B[N,768]^T (+ bias), fp16 operands.
// USE_ALO adds (A_lo @ B_hi). HALF_OUT writes __half C.
// BM=128, BN=256, BK=32, 8 warps (2x4), warp tile 64x64.
// 3-stage cp.async, single __syncthreads per chunk.
// ---------------------------------------------------------------------------
#define GBM 128
#define GBN 256
#define GBK 32
#define GNCH (768 / GBK)         // 24
#define ROWB 80                  // smem row stride bytes (32 halves + 8 pad)
#define OFF_ALO 10240

template <bool USE_ALO>
__device__ __forceinline__ void gemm_load_chunk(
    uint32_t buf,
    const __half* __restrict__ Ahi, const __half* __restrict__ Alo,
    const __half* __restrict__ Bhi,
    int rowBase, int colBase, int k0, int tid)
{
    constexpr uint32_t OFF_B = USE_ALO ? 20480u : 10240u;
    // A: 128 rows x 4 units
#pragma unroll
    for (int it = 0; it < 2; it++) {
        int t = tid + it * 256;
        int r = t >> 2, c = t & 3;
        uint32_t soff = (uint32_t)(r * ROWB + c * 16);
        size_t ga = (size_t)(rowBase + r) * 768 + k0 + c * 8;
        cp16(buf + soff, Ahi + ga);
        if (USE_ALO) cp16(buf + OFF_ALO + soff, Alo + ga);
    }
    // B: 256 rows x 4 units
#pragma unroll
    for (int it = 0; it < 4; it++) {
        int t = tid + it * 256;
        int r = t >> 2, c = t & 3;
        uint32_t soff = (uint32_t)(r * ROWB + c * 16);
        size_t gb = (size_t)(colBase + r) * 768 + k0 + c * 8;
        cp16(buf + OFF_B + soff, Bhi + gb);
    }
    cp_commit();
}

template <bool USE_ALO, bool HALF_OUT>
__global__ void __launch_bounds__(256)
wmma_gemm(const __half* __restrict__ Ahi, const __half* __restrict__ Alo,
          const __half* __restrict__ Bhi,
          const float* __restrict__ bias, void* __restrict__ Cv, int N)
{
    constexpr uint32_t OFF_B = USE_ALO ? 20480u : 10240u;
    constexpr uint32_t STG = USE_ALO ? 40960u : 30720u;

    const uint32_t sb = smem_u32(smem_raw);
    const int tid   = threadIdx.x;
    const int lane  = tid & 31;
    const int wid   = tid >> 5;
    const int warpM = wid >> 2;           // 0..1  (rows 64*warpM)
    const int warpN = wid & 3;            // 0..3  (cols 64*warpN)
    const int rowBase = blockIdx.y * GBM;
    const int colBase = blockIdx.x * GBN;

    float acc[4][8][4];
#pragma unroll
    for (int i = 0; i < 4; i++)
#pragma unroll
        for (int j = 0; j < 8; j++)
#pragma unroll
            for (int e = 0; e < 4; e++) acc[i][j][e] = 0.f;

    const uint32_t a_lane = (uint32_t)((warpM * 64 + (lane & 15)) * ROWB + (lane >> 4) * 16);
    const uint32_t b_lane = OFF_B
        + (uint32_t)((warpN * 64 + ((lane & 7) | ((lane >> 4) << 3))) * ROWB
                     + ((lane >> 3) & 1) * 16);

    gemm_load_chunk<USE_ALO>(sb,       Ahi, Alo, Bhi, rowBase, colBase, 0,   tid);
    gemm_load_chunk<USE_ALO>(sb + STG, Ahi, Alo, Bhi, rowBase, colBase, GBK, tid);

    for (int ch = 0; ch < GNCH; ch++) {
        if (ch < GNCH - 1) cp_wait<1>(); else cp_wait<0>();
        __syncthreads();
        if (ch + 2 < GNCH)
            gemm_load_chunk<USE_ALO>(sb + (uint32_t)((ch + 2) % 3) * STG,
                                     Ahi, Alo, Bhi, rowBase, colBase,
                                     (ch + 2) * GBK, tid);
        const uint32_t buf = sb + (uint32_t)(ch % 3) * STG;

#pragma unroll
        for (int k16 = 0; k16 < 2; k16++) {
            const uint32_t kb = (uint32_t)(k16 * 32);
            uint32_t ah[4][4], al[4][4];
#pragma unroll
            for (int mt = 0; mt < 4; mt++) {
                uint32_t ao = buf + a_lane + kb + (uint32_t)(mt * 16 * ROWB);
                ldm_x4(ah[mt], ao);
                if (USE_ALO) ldm_x4(al[mt], ao + OFF_ALO);
            }
            uint32_t bh[4][4];
#pragma unroll
            for (int p = 0; p < 4; p++)
                ldm_x4(bh[p], buf + b_lane + kb + (uint32_t)(p * 16 * ROWB));
#pragma unroll
            for (int mt = 0; mt < 4; mt++)
#pragma unroll
                for (int p = 0; p < 4; p++) {
                    mma16816h(acc[mt][2 * p + 0], ah[mt], &bh[p][0]);
                    if (USE_ALO) mma16816h(acc[mt][2 * p + 0], al[mt], &bh[p][0]);
                    mma16816h(acc[mt][2 * p + 1], ah[mt], &bh[p][2]);
                    if (USE_ALO) mma16816h(acc[mt][2 * p + 1], al[mt], &bh[p][2]);
                }
        }
    }

#pragma unroll
    for (int mt = 0; mt < 4; mt++) {
        const int row0 = rowBase + warpM * 64 + mt * 16 + (lane >> 2);
#pragma unroll
        for (int nt = 0; nt < 8; nt++) {
            const int col = colBase + warpN * 64 + nt * 8 + (lane & 3) * 2;
            float b0 = 0.f, b1 = 0.f;
            if (bias != nullptr) { b0 = bias[col]; b1 = bias[col + 1]; }
            if (HALF_OUT) {
                __half* Ch = (__half*)Cv;
                *(__half2*)&Ch[(size_t)row0 * N + col] =
                    __floats2half2_rn(acc[mt][nt][0] + b0, acc[mt][nt][1] + b1);
                *(__half2*)&Ch[(size_t)(row0 + 8) * N + col] =
                    __floats2half2_rn(acc[mt][nt][2] + b0, acc[mt][nt][3] + b1);
            } else {
                float* C = (float*)Cv;
                *(float2*)&C[(size_t)row0 * N + col] =
                    make_float2(acc[mt][nt][0] + b0, acc[mt][nt][1] + b1);
                *(float2*)&C[(size_t)(row0 + 8) * N + col] =
                    make_float2(acc[mt][nt][2] + b0, acc[mt][nt][3] + b1);
            }
        }
    }
}

// ---------------------------------------------------------------------------
// fp32 -> fp16 round (for x)
// ---------------------------------------------------------------------------
__global__ void round_fp32(const float* __restrict__ src,
                           __half* __restrict__ hi, size_t n4)
{
    size_t i = (size_t)blockIdx.x * blockDim.x + threadIdx.x;
    if (i >= n4) return;
    float4 v = ((const float4*)src)[i];
    __half2* hp = (__half2*)hi;
    hp[i * 2 + 0] = __halves2half2(__float2half(v.x), __float2half(v.y));
    hp[i * 2 + 1] = __halves2half2(__float2half(v.z), __float2half(v.w));
}

// ---------------------------------------------------------------------------
// W [K,N] row-major -> [N,K] K-major fp16 (transpose + round)
// ---------------------------------------------------------------------------
__global__ void transpose_round(const float* __restrict__ W,
                                __half* __restrict__ hi, int K, int N)
{
    __shared__ float t[32][33];
    int n0 = blockIdx.x * 32, k0 = blockIdx.y * 32;
    for (int r = threadIdx.y; r < 32; r += 8)
        t[r][threadIdx.x] = W[(size_t)(k0 + r) * N + n0 + threadIdx.x];
    __syncthreads();
    for (int r = threadIdx.y; r < 32; r += 8) {
        float v = t[threadIdx.x][r];
        hi[(size_t)(n0 + r) * K + k0 + threadIdx.x] = __float2half(v);
    }
}

// ---------------------------------------------------------------------------
// Fused MMA attention, all fp16 (R9). Grid (LWIN, NHEADS, B), 13 warps.
// ---------------------------------------------------------------------------
#define AROW   144
#define SQ_O   0
#define SK_O   29952
#define SV_O   59904
#define ATT_SMEM 89856
#define ATT_THREADS 416

__global__ void __launch_bounds__(ATT_THREADS)
win_attn_mma()
{
    const uint32_t sb = smem_u32(smem_raw);
    const int l    = blockIdx.x;
    const int head = blockIdx.y;
    const int b    = blockIdx.z;
    const int wy   = l / NW_WIN;
    const int wx   = l % NW_WIN;
    const int tid  = threadIdx.x;
    const int lane = tid & 31;
    const int w    = tid >> 5;       // 0..12

    // ---- stage Q,K,V (fp16) into smem; zero-fill pad rows ----
#pragma unroll
    for (int it = 0; it < 12; it++) {
        int idx = tid + it * ATT_THREADS;   // 0..4991
        int arr = idx / 1664;               // 0=Q 1=K 2=V
        int rem = idx - arr * 1664;
        int row = rem >> 3;                 // 0..207
        int c   = rem & 7;                  // 16B unit
        uint32_t soff = (uint32_t)(arr * SK_O + row * AROW + c * 16);
        int rr = row / WIN, cc = row % WIN;
        int hh = wy * WIN + rr, ww = wx * WIN + cc;
        if (row < NWTOK && hh < H_IMG && ww < W_IMG) {
            size_t gbase = ((size_t)(b * NTOK + hh * W_IMG + ww)) * QKV_DIM
                           + (size_t)head * HDIM + (size_t)arr * C_DIM + c * 8;
            cp16(sb + soff, g_qkvh + gbase);
        } else {
            *(uint4*)(smem_raw + soff) = make_uint4(0, 0, 0, 0);
        }
    }
    cp_commit();
    cp_wait<0>();
    __syncthreads();

    const uint32_t a_lane  = sb + SQ_O
        + (uint32_t)((w * 16 + (lane & 15)) * AROW + (lane >> 4) * 16);
    const uint32_t kb_lane = sb + SK_O
        + (uint32_t)((((lane & 7) | ((lane >> 4) << 3))) * AROW + ((lane >> 3) & 1) * 16);
    const uint32_t vb_lane = sb + SV_O
        + (uint32_t)(((((lane >> 3) & 1) * 8 + (lane & 7))) * AROW + (lane >> 4) * 16);

    uint32_t qa[4][4];
#pragma unroll
    for (int kt = 0; kt < 4; kt++) ldm_x4(qa[kt], a_lane + kt * 32);

    const int cq = 2 * (lane & 3);

    // ---- pass 1: row max ----
    float m0 = -1e30f, m1 = -1e30f;
    for (int t = 0; t < 13; t++) {
        float s0[4] = {0.f, 0.f, 0.f, 0.f}, s1[4] = {0.f, 0.f, 0.f, 0.f};
#pragma unroll
        for (int kt = 0; kt < 4; kt++) {
            uint32_t kb[4];
            ldm_x4(kb, kb_lane + (uint32_t)(t * 16 * AROW + kt * 32));
            mma16816h(s0, qa[kt], &kb[0]);
            mma16816h(s1, qa[kt], &kb[2]);
        }
        int j0 = t * 16 + cq;
        int j1 = j0 + 8;
        if (j0     < NWTOK) { m0 = fmaxf(m0, s0[0]); m1 = fmaxf(m1, s0[2]); }
        if (j0 + 1 < NWTOK) { m0 = fmaxf(m0, s0[1]); m1 = fmaxf(m1, s0[3]); }
        if (j1     < NWTOK) { m0 = fmaxf(m0, s1[0]); m1 = fmaxf(m1, s1[2]); }
        if (j1 + 1 < NWTOK) { m0 = fmaxf(m0, s1[1]); m1 = fmaxf(m1, s1[3]); }
    }
    m0 *= 0.125f;  m1 *= 0.125f;
#pragma unroll
    for (int off = 1; off <= 2; off <<= 1) {
        m0 = fmaxf(m0, __shfl_xor_sync(0xffffffffu, m0, off));
        m1 = fmaxf(m1, __shfl_xor_sync(0xffffffffu, m1, off));
    }

    // ---- pass 2: recompute S, P = exp(s*0.125 - m), O += P@V ----
    float o[8][4];
#pragma unroll
    for (int i = 0; i < 8; i++)
#pragma unroll
        for (int e = 0; e < 4; e++) o[i][e] = 0.f;
    float sum0 = 0.f, sum1 = 0.f;

    for (int t = 0; t < 13; t++) {
        float s0[4] = {0.f, 0.f, 0.f, 0.f}, s1[4] = {0.f, 0.f, 0.f, 0.f};
#pragma unroll
        for (int kt = 0; kt < 4; kt++) {
            uint32_t kb[4];
            ldm_x4(kb, kb_lane + (uint32_t)(t * 16 * AROW + kt * 32));
            mma16816h(s0, qa[kt], &kb[0]);
            mma16816h(s1, qa[kt], &kb[2]);
        }
        int j0 = t * 16 + cq;
        int j1 = j0 + 8;
        float p0 = (j0     < NWTOK) ? __expf(s0[0] * 0.125f - m0) : 0.f;
        float p1 = (j0 + 1 < NWTOK) ? __expf(s0[1] * 0.125f - m0) : 0.f;
        float p2 = (j0     < NWTOK) ? __expf(s0[2] * 0.125f - m1) : 0.f;
        float p3 = (j0 + 1 < NWTOK) ? __expf(s0[3] * 0.125f - m1) : 0.f;
        float u0 = (j1     < NWTOK) ? __expf(s1[0] * 0.125f - m0) : 0.f;
        float u1 = (j1 + 1 < NWTOK) ? __expf(s1[1] * 0.125f - m0) : 0.f;
        float u2 = (j1     < NWTOK) ? __expf(s1[2] * 0.125f - m1) : 0.f;
        float u3 = (j1 + 1 < NWTOK) ? __expf(s1[3] * 0.125f - m1) : 0.f;
        sum0 += p0 + p1 + u0 + u1;
        sum1 += p2 + p3 + u2 + u3;

        uint32_t pah[4], pal[4];
        pah[0] = pack_f16(p0, p1);  pah[1] = pack_f16(p2, p3);
        pah[2] = pack_f16(u0, u1);  pah[3] = pack_f16(u2, u3);
        {
            float q0 = __half2float(__low2half(*(__half2*)&pah[0]));
            float q1 = __half2float(__high2half(*(__half2*)&pah[0]));
            float q2 = __half2float(__low2half(*(__half2*)&pah[1]));
            float q3 = __half2float(__high2half(*(__half2*)&pah[1]));
            float r0 = __half2float(__low2half(*(__half2*)&pah[2]));
            float r1 = __half2float(__high2half(*(__half2*)&pah[2]));
            float r2 = __half2float(__low2half(*(__half2*)&pah[3]));
            float r3 = __half2float(__high2half(*(__half2*)&pah[3]));
            pal[0] = pack_f16(p0 - q0, p1 - q1);
            pal[1] = pack_f16(p2 - q2, p3 - q3);
            pal[2] = pack_f16(u0 - r0, u1 - r1);
            pal[3] = pack_f16(u2 - r2, u3 - r3);
        }

#pragma unroll
        for (int dg = 0; dg < 4; dg++) {
            uint32_t vb[4];
            ldm_x4_t(vb, vb_lane + (uint32_t)(t * 16 * AROW + dg * 32));
            mma16816h(o[dg * 2 + 0], pah, &vb[0]);
            mma16816h(o[dg * 2 + 0], pal, &vb[0]);
            mma16816h(o[dg * 2 + 1], pah, &vb[2]);
            mma16816h(o[dg * 2 + 1], pal, &vb[2]);
        }
    }
#pragma unroll
    for (int off = 1; off <= 2; off <<= 1) {
        sum0 += __shfl_xor_sync(0xffffffffu, sum0, off);
        sum1 += __shfl_xor_sync(0xffffffffu, sum1, off);
    }
    const float inv0 = 1.f / sum0;
    const float inv1 = 1.f / sum1;

    // ---- epilogue: O/sum -> g_atthi/lo (fp16 hi/lo split) ----
    const int r0 = w * 16 + (lane >> 2);
#pragma unroll
    for (int half = 0; half < 2; half++) {
        const int row = r0 + half * 8;
        if (row >= NWTOK) continue;
        const int rr = row / WIN, cc = row % WIN;
        const int hh = wy * WIN + rr, ww = wx * WIN + cc;
        if (hh >= H_IMG || ww >= W_IMG) continue;
        const float inv = half ? inv1 : inv0;
        const size_t obase = ((size_t)(b * NTOK + hh * W_IMG + ww)) * C_DIM
                             + (size_t)head * HDIM;
#pragma unroll
        for (int dt = 0; dt < 8; dt++) {
            const int col = dt * 8 + cq;
            float v0 = o[dt][half * 2 + 0] * inv;
            float v1 = o[dt][half * 2 + 1] * inv;
            __half h0 = __float2half(v0);
            __half h1 = __float2half(v1);
            *(__half2*)&g_atthi[obase + col] = __halves2half2(h0, h1);
            *(__half2*)&g_attlo[obase + col] = __halves2half2(
                __float2half(v0 - __half2float(h0)),
                __float2half(v1 - __half2float(h1)));
        }
    }
}

// ---------------------------------------------------------------------------
// Launch
// ---------------------------------------------------------------------------
extern "C" void kernel_launch(void* const* d_in, const int* in_sizes, int n_in,
                              void* d_out, int out_size)
{
    const float* x     = (const float*)d_in[0];
    const float* Wqkv  = (const float*)d_in[1];
    const float* Wproj = (const float*)d_in[2];
    const float* bproj = (const float*)d_in[3];
    float* out = (float*)d_out;

    __half *qkvh, *xhi, *wqh, *wph, *athi, *atlo;
    cudaGetSymbolAddress((void**)&qkvh, g_qkvh);
    cudaGetSymbolAddress((void**)&xhi,  g_xhi);
    cudaGetSymbolAddress((void**)&wqh,  g_wqkv_hi);
    cudaGetSymbolAddress((void**)&wph,  g_wproj_hi);
    cudaGetSymbolAddress((void**)&athi, g_atthi);
    cudaGetSymbolAddress((void**)&atlo, g_attlo);

    // convert x + weights to fp16
    {
        size_t n4 = (size_t)MTOT * C_DIM / 4;
        round_fp32<<<(unsigned)((n4 + 255) / 256), 256>>>(x, xhi, n4);
        transpose_round<<<dim3(QKV_DIM / 32, C_DIM / 32), dim3(32, 8)>>>(Wqkv, wqh, C_DIM, QKV_DIM);
        transpose_round<<<dim3(C_DIM / 32,  C_DIM / 32), dim3(32, 8)>>>(Wproj, wph, C_DIM, C_DIM);
    }

    const int smem1 = 3 * 30720;   // stage 1 (A + B)
    const int smem3 = 3 * 40960;   // stage 3 (A hi/lo + B)
    cudaFuncSetAttribute((const void*)wmma_gemm<false, true>,
                         cudaFuncAttributeMaxDynamicSharedMemorySize, smem1);
    cudaFuncSetAttribute((const void*)wmma_gemm<true, false>,
                         cudaFuncAttributeMaxDynamicSharedMemorySize, smem3);
    cudaFuncSetAttribute((const void*)win_attn_mma,
                         cudaFuncAttributeMaxDynamicSharedMemorySize, ATT_SMEM);

    // Stage 1: qkv(fp16) = x @ Wqkv  (plain fp16; logit error attenuated)
    wmma_gemm<false, true><<<dim3(QKV_DIM / GBN, MTOT / GBM), 256, smem1>>>(
        xhi, nullptr, wqh, nullptr, (void*)qkvh, QKV_DIM);

    // Stage 2: fused all-fp16 MMA attention
    win_attn_mma<<<dim3(LWIN, NHEADS, B_SZ), ATT_THREADS, ATT_SMEM>>>();

    // Stage 3: out = att @ Wproj + bproj (2-term split, fp32 out)
    wmma_gemm<true, false><<<dim3(C_DIM / GBN, MTOT / GBM), 256, smem3>>>(
        athi, atlo, wph, bproj, (void*)out, C_DIM);
}

// round 12
// speedup vs baseline: 1.1324x; 1.1324x over previous
#include <cuda_runtime.h>
#include <cuda_bf16.h>
#include <cuda_fp16.h>
#include <math.h>
#include <stdint.h>

// ---------------------------------------------------------------------------
// WindowedAttention on GB300 (sm_103a chip; ptxas target is base sm_103 so
// tcgen05 unavailable — warp-level mma.sync tensor cores).
// R11: revert to R9 GEMM shape (BM=BN=128, warp 64x32, 2 CTA/SM);
//      stage 1 uses BK=64 (12 chunks -> half the barrier/drain events);
//      stage 3 BK=32 fp16 2-term split; attention all-fp16 (R9).
// ---------------------------------------------------------------------------

#define C_DIM    768
#define QKV_DIM  2304
#define B_SZ     8
#define H_IMG    80
#define W_IMG    80
#define NTOK     (H_IMG * W_IMG)     // 6400
#define WIN      14
#define NW_WIN   6
#define LWIN     36
#define NWTOK    (WIN * WIN)         // 196
#define NHEADS   12
#define HDIM     64
#define MTOT     (B_SZ * NTOK)       // 51200

// ---------------- scratch (__device__ globals: allocation-free rule) -------
__device__ __half  g_qkvh[(size_t)MTOT * QKV_DIM];     // fp16 qkv
__device__ __half  g_xhi[(size_t)MTOT * C_DIM];
__device__ __half  g_wqkv_hi[(size_t)QKV_DIM * C_DIM]; // [N,K] K-major
__device__ __half  g_wproj_hi[(size_t)C_DIM * C_DIM];  // [N,K] K-major
__device__ __half  g_atthi[(size_t)MTOT * C_DIM];
__device__ __half  g_attlo[(size_t)MTOT * C_DIM];

extern __shared__ char smem_raw[];

// ---------------------------- PTX helpers ----------------------------------
__device__ __forceinline__ uint32_t smem_u32(const void* p) {
    uint32_t a;
    asm("{ .reg .u64 t; cvta.to.shared.u64 t, %1; cvt.u32.u64 %0, t; }"
        : "=r"(a) : "l"(p));
    return a;
}
__device__ __forceinline__ void cp16(uint32_t saddr, const void* g) {
    asm volatile("cp.async.cg.shared.global [%0], [%1], 16;" :: "r"(saddr), "l"(g));
}
__device__ __forceinline__ void cp_commit() { asm volatile("cp.async.commit_group;" ::: "memory"); }
template <int N> __device__ __forceinline__ void cp_wait() {
    asm volatile("cp.async.wait_group %0;" :: "n"(N) : "memory");
}
__device__ __forceinline__ void ldm_x4(uint32_t* r, uint32_t addr) {
    asm volatile("ldmatrix.sync.aligned.m8n8.x4.shared.b16 {%0,%1,%2,%3}, [%4];"
        : "=r"(r[0]), "=r"(r[1]), "=r"(r[2]), "=r"(r[3]) : "r"(addr));
}
__device__ __forceinline__ void ldm_x4_t(uint32_t* r, uint32_t addr) {
    asm volatile("ldmatrix.sync.aligned.m8n8.x4.trans.shared.b16 {%0,%1,%2,%3}, [%4];"
        : "=r"(r[0]), "=r"(r[1]), "=r"(r[2]), "=r"(r[3]) : "r"(addr));
}
// fp16 MMA, fp32 accum
__device__ __forceinline__ void mma16816h(float* d, const uint32_t* a, const uint32_t* b) {
    asm volatile(
        "mma.sync.aligned.m16n8k16.row.col.f32.f16.f16.f32 "
        "{%0,%1,%2,%3}, {%4,%5,%6,%7}, {%8,%9}, {%0,%1,%2,%3};"
        : "+f"(d[0]), "+f"(d[1]), "+f"(d[2]), "+f"(d[3])
        : "r"(a[0]), "r"(a[1]), "r"(a[2]), "r"(a[3]), "r"(b[0]), "r"(b[1]));
}
__device__ __forceinline__ uint32_t pack_f16(float lo, float hi) {
    __half2 h = __floats2half2_rn(lo, hi);
    return *(uint32_t*)&h;
}

// ---------------------------------------------------------------------------
// Warp-MMA GEMM: C[M,N] = A[M,768] @ B[N,768]^T (+ bias), fp16 operands.
// Template: BK (32 or 64), USE_ALO (adds A_lo @ B term), HALF_OUT.
// BM=BN=128, 8 warps (2x4), warp tile 64x32, 3-stage cp.async,
// single __syncthreads per chunk.
// Row stride = BK*2 + 16 bytes: multiples mod 128 cover all eight 16B
// groups -> conflict-free ldmatrix (verified for 80 and 144).
// ---------------------------------------------------------------------------
#define GBM 128
#define GBN 128

template <int BK, bool USE_ALO>
__device__ __forceinline__ void gemm_load_chunk(
    uint32_t buf,
    const __half* __restrict__ Ahi, const __half* __restrict__ Alo,
    const __half* __restrict__ Bhi,
    int rowBase, int colBase, int k0, int tid)
{
    constexpr int UNITS = BK / 8;                 // 16B units per row
    constexpr int ROWBT = BK * 2 + 16;            // bytes per smem row
    constexpr uint32_t TILE = 128u * ROWBT;
    constexpr uint32_t B_OFF = TILE * (USE_ALO ? 2u : 1u);
    constexpr int ITER = 128 * UNITS / 256;
#pragma unroll
    for (int it = 0; it < ITER; it++) {
        int t = tid + it * 256;
        int r = t / UNITS, c = t % UNITS;
        uint32_t soff = (uint32_t)(r * ROWBT + c * 16);
        size_t ga = (size_t)(rowBase + r) * 768 + k0 + c * 8;
        size_t gb = (size_t)(colBase + r) * 768 + k0 + c * 8;
        cp16(buf + soff, Ahi + ga);
        if (USE_ALO) cp16(buf + TILE + soff, Alo + ga);
        cp16(buf + B_OFF + soff, Bhi + gb);
    }
    cp_commit();
}

template <int BK, bool USE_ALO, bool HALF_OUT>
__global__ void __launch_bounds__(256)
wmma_gemm(const __half* __restrict__ Ahi, const __half* __restrict__ Alo,
          const __half* __restrict__ Bhi,
          const float* __restrict__ bias, void* __restrict__ Cv, int N)
{
    constexpr int ROWBT = BK * 2 + 16;
    constexpr uint32_t TILE = 128u * ROWBT;
    constexpr uint32_t B_OFF = TILE * (USE_ALO ? 2u : 1u);
    constexpr uint32_t STG = TILE * (USE_ALO ? 3u : 2u);
    constexpr int GNCH = 768 / BK;
    constexpr int NK16 = BK / 16;

    const uint32_t sb = smem_u32(smem_raw);
    const int tid   = threadIdx.x;
    const int lane  = tid & 31;
    const int wid   = tid >> 5;
    const int warpM = wid >> 2;
    const int warpN = wid & 3;
    const int rowBase = blockIdx.y * GBM;
    const int colBase = blockIdx.x * GBN;

    float acc[4][4][4];
#pragma unroll
    for (int i = 0; i < 4; i++)
#pragma unroll
        for (int j = 0; j < 4; j++)
#pragma unroll
            for (int e = 0; e < 4; e++) acc[i][j][e] = 0.f;

    const uint32_t a_lane = (uint32_t)((warpM * 64 + (lane & 15)) * ROWBT + (lane >> 4) * 16);
    const uint32_t b_lane = B_OFF
        + (uint32_t)((warpN * 32 + ((lane & 7) | ((lane >> 4) << 3))) * ROWBT
                     + ((lane >> 3) & 1) * 16);

    gemm_load_chunk<BK, USE_ALO>(sb,       Ahi, Alo, Bhi, rowBase, colBase, 0,  tid);
    gemm_load_chunk<BK, USE_ALO>(sb + STG, Ahi, Alo, Bhi, rowBase, colBase, BK, tid);

    for (int ch = 0; ch < GNCH; ch++) {
        if (ch < GNCH - 1) cp_wait<1>(); else cp_wait<0>();
        __syncthreads();
        // safe: sync proves all warps finished compute(ch-1), the last
        // consumer of buffer (ch+2)%3.
        if (ch + 2 < GNCH)
            gemm_load_chunk<BK, USE_ALO>(sb + (uint32_t)((ch + 2) % 3) * STG,
                                         Ahi, Alo, Bhi, rowBase, colBase,
                                         (ch + 2) * BK, tid);
        const uint32_t buf = sb + (uint32_t)(ch % 3) * STG;

#pragma unroll
        for (int k16 = 0; k16 < NK16; k16++) {
            const uint32_t kb = (uint32_t)(k16 * 32);
            uint32_t ah[4][4], al[4][4];
#pragma unroll
            for (int mt = 0; mt < 4; mt++) {
                uint32_t ao = buf + a_lane + kb + (uint32_t)(mt * 16 * ROWBT);
                ldm_x4(ah[mt], ao);
                if (USE_ALO) ldm_x4(al[mt], ao + TILE);
            }
            uint32_t bh[2][4];
#pragma unroll
            for (int half = 0; half < 2; half++)
                ldm_x4(bh[half], buf + b_lane + kb + (uint32_t)(half * 16 * ROWBT));
#pragma unroll
            for (int mt = 0; mt < 4; mt++)
#pragma unroll
                for (int nt = 0; nt < 4; nt++) {
                    const uint32_t* bhf = &bh[nt >> 1][(nt & 1) * 2];
                    mma16816h(acc[mt][nt], ah[mt], bhf);
                    if (USE_ALO) mma16816h(acc[mt][nt], al[mt], bhf);
                }
        }
    }

#pragma unroll
    for (int mt = 0; mt < 4; mt++) {
        const int row0 = rowBase + warpM * 64 + mt * 16 + (lane >> 2);
#pragma unroll
        for (int nt = 0; nt < 4; nt++) {
            const int col = colBase + warpN * 32 + nt * 8 + (lane & 3) * 2;
            float b0 = 0.f, b1 = 0.f;
            if (bias != nullptr) { b0 = bias[col]; b1 = bias[col + 1]; }
            if (HALF_OUT) {
                __half* Ch = (__half*)Cv;
                *(__half2*)&Ch[(size_t)row0 * N + col] =
                    __floats2half2_rn(acc[mt][nt][0] + b0, acc[mt][nt][1] + b1);
                *(__half2*)&Ch[(size_t)(row0 + 8) * N + col] =
                    __floats2half2_rn(acc[mt][nt][2] + b0, acc[mt][nt][3] + b1);
            } else {
                float* C = (float*)Cv;
                *(float2*)&C[(size_t)row0 * N + col] =
                    make_float2(acc[mt][nt][0] + b0, acc[mt][nt][1] + b1);
                *(float2*)&C[(size_t)(row0 + 8) * N + col] =
                    make_float2(acc[mt][nt][2] + b0, acc[mt][nt][3] + b1);
            }
        }
    }
}

// ---------------------------------------------------------------------------
// fp32 -> fp16 round (for x)
// ---------------------------------------------------------------------------
__global__ void round_fp32(const float* __restrict__ src,
                           __half* __restrict__ hi, size_t n4)
{
    size_t i = (size_t)blockIdx.x * blockDim.x + threadIdx.x;
    if (i >= n4) return;
    float4 v = ((const float4*)src)[i];
    __half2* hp = (__half2*)hi;
    hp[i * 2 + 0] = __halves2half2(__float2half(v.x), __float2half(v.y));
    hp[i * 2 + 1] = __halves2half2(__float2half(v.z), __float2half(v.w));
}

// ---------------------------------------------------------------------------
// W [K,N] row-major -> [N,K] K-major fp16 (transpose + round)
// ---------------------------------------------------------------------------
__global__ void transpose_round(const float* __restrict__ W,
                                __half* __restrict__ hi, int K, int N)
{
    __shared__ float t[32][33];
    int n0 = blockIdx.x * 32, k0 = blockIdx.y * 32;
    for (int r = threadIdx.y; r < 32; r += 8)
        t[r][threadIdx.x] = W[(size_t)(k0 + r) * N + n0 + threadIdx.x];
    __syncthreads();
    for (int r = threadIdx.y; r < 32; r += 8) {
        float v = t[threadIdx.x][r];
        hi[(size_t)(n0 + r) * K + k0 + threadIdx.x] = __float2half(v);
    }
}

// ---------------------------------------------------------------------------
// Fused MMA attention, all fp16 (R9). Grid (LWIN, NHEADS, B), 13 warps.
// ---------------------------------------------------------------------------
#define AROW   144
#define SQ_O   0
#define SK_O   29952
#define SV_O   59904
#define ATT_SMEM 89856
#define ATT_THREADS 416

__global__ void __launch_bounds__(ATT_THREADS)
win_attn_mma()
{
    const uint32_t sb = smem_u32(smem_raw);
    const int l    = blockIdx.x;
    const int head = blockIdx.y;
    const int b    = blockIdx.z;
    const int wy   = l / NW_WIN;
    const int wx   = l % NW_WIN;
    const int tid  = threadIdx.x;
    const int lane = tid & 31;
    const int w    = tid >> 5;       // 0..12

    // ---- stage Q,K,V (fp16) into smem; zero-fill pad rows ----
#pragma unroll
    for (int it = 0; it < 12; it++) {
        int idx = tid + it * ATT_THREADS;   // 0..4991
        int arr = idx / 1664;               // 0=Q 1=K 2=V
        int rem = idx - arr * 1664;
        int row = rem >> 3;                 // 0..207
        int c   = rem & 7;                  // 16B unit
        uint32_t soff = (uint32_t)(arr * SK_O + row * AROW + c * 16);
        int rr = row / WIN, cc = row % WIN;
        int hh = wy * WIN + rr, ww = wx * WIN + cc;
        if (row < NWTOK && hh < H_IMG && ww < W_IMG) {
            size_t gbase = ((size_t)(b * NTOK + hh * W_IMG + ww)) * QKV_DIM
                           + (size_t)head * HDIM + (size_t)arr * C_DIM + c * 8;
            cp16(sb + soff, g_qkvh + gbase);
        } else {
            *(uint4*)(smem_raw + soff) = make_uint4(0, 0, 0, 0);
        }
    }
    cp_commit();
    cp_wait<0>();
    __syncthreads();

    const uint32_t a_lane  = sb + SQ_O
        + (uint32_t)((w * 16 + (lane & 15)) * AROW + (lane >> 4) * 16);
    const uint32_t kb_lane = sb + SK_O
        + (uint32_t)((((lane & 7) | ((lane >> 4) << 3))) * AROW + ((lane >> 3) & 1) * 16);
    const uint32_t vb_lane = sb + SV_O
        + (uint32_t)(((((lane >> 3) & 1) * 8 + (lane & 7))) * AROW + (lane >> 4) * 16);

    uint32_t qa[4][4];
#pragma unroll
    for (int kt = 0; kt < 4; kt++) ldm_x4(qa[kt], a_lane + kt * 32);

    const int cq = 2 * (lane & 3);

    // ---- pass 1: row max ----
    float m0 = -1e30f, m1 = -1e30f;
    for (int t = 0; t < 13; t++) {
        float s0[4] = {0.f, 0.f, 0.f, 0.f}, s1[4] = {0.f, 0.f, 0.f, 0.f};
#pragma unroll
        for (int kt = 0; kt < 4; kt++) {
            uint32_t kb[4];
            ldm_x4(kb, kb_lane + (uint32_t)(t * 16 * AROW + kt * 32));
            mma16816h(s0, qa[kt], &kb[0]);
            mma16816h(s1, qa[kt], &kb[2]);
        }
        int j0 = t * 16 + cq;
        int j1 = j0 + 8;
        if (j0     < NWTOK) { m0 = fmaxf(m0, s0[0]); m1 = fmaxf(m1, s0[2]); }
        if (j0 + 1 < NWTOK) { m0 = fmaxf(m0, s0[1]); m1 = fmaxf(m1, s0[3]); }
        if (j1     < NWTOK) { m0 = fmaxf(m0, s1[0]); m1 = fmaxf(m1, s1[2]); }
        if (j1 + 1 < NWTOK) { m0 = fmaxf(m0, s1[1]); m1 = fmaxf(m1, s1[3]); }
    }
    m0 *= 0.125f;  m1 *= 0.125f;
#pragma unroll
    for (int off = 1; off <= 2; off <<= 1) {
        m0 = fmaxf(m0, __shfl_xor_sync(0xffffffffu, m0, off));
        m1 = fmaxf(m1, __shfl_xor_sync(0xffffffffu, m1, off));
    }

    // ---- pass 2: recompute S, P = exp(s*0.125 - m), O += P@V ----
    float o[8][4];
#pragma unroll
    for (int i = 0; i < 8; i++)
#pragma unroll
        for (int e = 0; e < 4; e++) o[i][e] = 0.f;
    float sum0 = 0.f, sum1 = 0.f;

    for (int t = 0; t < 13; t++) {
        float s0[4] = {0.f, 0.f, 0.f, 0.f}, s1[4] = {0.f, 0.f, 0.f, 0.f};
#pragma unroll
        for (int kt = 0; kt < 4; kt++) {
            uint32_t kb[4];
            ldm_x4(kb, kb_lane + (uint32_t)(t * 16 * AROW + kt * 32));
            mma16816h(s0, qa[kt], &kb[0]);
            mma16816h(s1, qa[kt], &kb[2]);
        }
        int j0 = t * 16 + cq;
        int j1 = j0 + 8;
        float p0 = (j0     < NWTOK) ? __expf(s0[0] * 0.125f - m0) : 0.f;
        float p1 = (j0 + 1 < NWTOK) ? __expf(s0[1] * 0.125f - m0) : 0.f;
        float p2 = (j0     < NWTOK) ? __expf(s0[2] * 0.125f - m1) : 0.f;
        float p3 = (j0 + 1 < NWTOK) ? __expf(s0[3] * 0.125f - m1) : 0.f;
        float u0 = (j1     < NWTOK) ? __expf(s1[0] * 0.125f - m0) : 0.f;
        float u1 = (j1 + 1 < NWTOK) ? __expf(s1[1] * 0.125f - m0) : 0.f;
        float u2 = (j1     < NWTOK) ? __expf(s1[2] * 0.125f - m1) : 0.f;
        float u3 = (j1 + 1 < NWTOK) ? __expf(s1[3] * 0.125f - m1) : 0.f;
        sum0 += p0 + p1 + u0 + u1;
        sum1 += p2 + p3 + u2 + u3;

        uint32_t pah[4], pal[4];
        pah[0] = pack_f16(p0, p1);  pah[1] = pack_f16(p2, p3);
        pah[2] = pack_f16(u0, u1);  pah[3] = pack_f16(u2, u3);
        {
            float q0 = __half2float(__low2half(*(__half2*)&pah[0]));
            float q1 = __half2float(__high2half(*(__half2*)&pah[0]));
            float q2 = __half2float(__low2half(*(__half2*)&pah[1]));
            float q3 = __half2float(__high2half(*(__half2*)&pah[1]));
            float r0 = __half2float(__low2half(*(__half2*)&pah[2]));
            float r1 = __half2float(__high2half(*(__half2*)&pah[2]));
            float r2 = __half2float(__low2half(*(__half2*)&pah[3]));
            float r3 = __half2float(__high2half(*(__half2*)&pah[3]));
            pal[0] = pack_f16(p0 - q0, p1 - q1);
            pal[1] = pack_f16(p2 - q2, p3 - q3);
            pal[2] = pack_f16(u0 - r0, u1 - r1);
            pal[3] = pack_f16(u2 - r2, u3 - r3);
        }

#pragma unroll
        for (int dg = 0; dg < 4; dg++) {
            uint32_t vb[4];
            ldm_x4_t(vb, vb_lane + (uint32_t)(t * 16 * AROW + dg * 32));
            mma16816h(o[dg * 2 + 0], pah, &vb[0]);
            mma16816h(o[dg * 2 + 0], pal, &vb[0]);
            mma16816h(o[dg * 2 + 1], pah, &vb[2]);
            mma16816h(o[dg * 2 + 1], pal, &vb[2]);
        }
    }
#pragma unroll
    for (int off = 1; off <= 2; off <<= 1) {
        sum0 += __shfl_xor_sync(0xffffffffu, sum0, off);
        sum1 += __shfl_xor_sync(0xffffffffu, sum1, off);
    }
    const float inv0 = 1.f / sum0;
    const float inv1 = 1.f / sum1;

    // ---- epilogue: O/sum -> g_atthi/lo (fp16 hi/lo split) ----
    const int r0 = w * 16 + (lane >> 2);
#pragma unroll
    for (int half = 0; half < 2; half++) {
        const int row = r0 + half * 8;
        if (row >= NWTOK) continue;
        const int rr = row / WIN, cc = row % WIN;
        const int hh = wy * WIN + rr, ww = wx * WIN + cc;
        if (hh >= H_IMG || ww >= W_IMG) continue;
        const float inv = half ? inv1 : inv0;
        const size_t obase = ((size_t)(b * NTOK + hh * W_IMG + ww)) * C_DIM
                             + (size_t)head * HDIM;
#pragma unroll
        for (int dt = 0; dt < 8; dt++) {
            const int col = dt * 8 + cq;
            float v0 = o[dt][half * 2 + 0] * inv;
            float v1 = o[dt][half * 2 + 1] * inv;
            __half h0 = __float2half(v0);
            __half h1 = __float2half(v1);
            *(__half2*)&g_atthi[obase + col] = __halves2half2(h0, h1);
            *(__half2*)&g_attlo[obase + col] = __halves2half2(
                __float2half(v0 - __half2float(h0)),
                __float2half(v1 - __half2float(h1)));
        }
    }
}

// ---------------------------------------------------------------------------
// Launch
// ---------------------------------------------------------------------------
extern "C" void kernel_launch(void* const* d_in, const int* in_sizes, int n_in,
                              void* d_out, int out_size)
{
    const float* x     = (const float*)d_in[0];
    const float* Wqkv  = (const float*)d_in[1];
    const float* Wproj = (const float*)d_in[2];
    const float* bproj = (const float*)d_in[3];
    float* out = (float*)d_out;

    __half *qkvh, *xhi, *wqh, *wph, *athi, *atlo;
    cudaGetSymbolAddress((void**)&qkvh, g_qkvh);
    cudaGetSymbolAddress((void**)&xhi,  g_xhi);
    cudaGetSymbolAddress((void**)&wqh,  g_wqkv_hi);
    cudaGetSymbolAddress((void**)&wph,  g_wproj_hi);
    cudaGetSymbolAddress((void**)&athi, g_atthi);
    cudaGetSymbolAddress((void**)&atlo, g_attlo);

    // convert x + weights to fp16
    {
        size_t n4 = (size_t)MTOT * C_DIM / 4;
        round_fp32<<<(unsigned)((n4 + 255) / 256), 256>>>(x, xhi, n4);
        transpose_round<<<dim3(QKV_DIM / 32, C_DIM / 32), dim3(32, 8)>>>(Wqkv, wqh, C_DIM, QKV_DIM);
        transpose_round<<<dim3(C_DIM / 32,  C_DIM / 32), dim3(32, 8)>>>(Wproj, wph, C_DIM, C_DIM);
    }

    const int smem1 = 3 * 2 * 128 * 144;   // BK=64, A+B        = 110592
    const int smem3 = 3 * 3 * 128 * 80;    // BK=32, Ahi/Alo/B  = 92160
    cudaFuncSetAttribute((const void*)wmma_gemm<64, false, true>,
                         cudaFuncAttributeMaxDynamicSharedMemorySize, smem1);
    cudaFuncSetAttribute((const void*)wmma_gemm<32, true, false>,
                         cudaFuncAttributeMaxDynamicSharedMemorySize, smem3);
    cudaFuncSetAttribute((const void*)win_attn_mma,
                         cudaFuncAttributeMaxDynamicSharedMemorySize, ATT_SMEM);

    // Stage 1: qkv(fp16) = x @ Wqkv  (plain fp16; logit error attenuated)
    wmma_gemm<64, false, true><<<dim3(QKV_DIM / GBN, MTOT / GBM), 256, smem1>>>(
        xhi, nullptr, wqh, nullptr, (void*)qkvh, QKV_DIM);

    // Stage 2: fused all-fp16 MMA attention
    win_attn_mma<<<dim3(LWIN, NHEADS, B_SZ), ATT_THREADS, ATT_SMEM>>>();

    // Stage 3: out = att @ Wproj + bproj (2-term split, fp32 out)
    wmma_gemm<32, true, false><<<dim3(C_DIM / GBN, MTOT / GBM), 256, smem3>>>(
        athi, atlo, wph, bproj, (void*)out, C_DIM);
}

// round 16
// speedup vs baseline: 1.2970x; 1.1454x over previous
#include <cuda_runtime.h>
#include <cuda_bf16.h>
#include <cuda_fp16.h>
#include <math.h>
#include <stdint.h>

// ---------------------------------------------------------------------------
// WindowedAttention on GB300 (sm_103a chip; ptxas target is base sm_103 so
// tcgen05 unavailable — warp-level mma.sync tensor cores).
// R12: both GEMMs plain fp16, BK=64, single-sync 3-stage cp.async
//      (error budget: stage-1 logit error attenuated by softmax; stage-3
//      1-term adds ~2.8e-4, total ~5.3e-4 < 1e-3). Attention all-fp16 (R9).
// ---------------------------------------------------------------------------

#define C_DIM    768
#define QKV_DIM  2304
#define B_SZ     8
#define H_IMG    80
#define W_IMG    80
#define NTOK     (H_IMG * W_IMG)     // 6400
#define WIN      14
#define NW_WIN   6
#define LWIN     36
#define NWTOK    (WIN * WIN)         // 196
#define NHEADS   12
#define HDIM     64
#define MTOT     (B_SZ * NTOK)       // 51200

// ---------------- scratch (__device__ globals: allocation-free rule) -------
__device__ __half  g_qkvh[(size_t)MTOT * QKV_DIM];     // fp16 qkv
__device__ __half  g_xhi[(size_t)MTOT * C_DIM];
__device__ __half  g_wqkv_hi[(size_t)QKV_DIM * C_DIM]; // [N,K] K-major
__device__ __half  g_wproj_hi[(size_t)C_DIM * C_DIM];  // [N,K] K-major
__device__ __half  g_atthi[(size_t)MTOT * C_DIM];

extern __shared__ char smem_raw[];

// ---------------------------- PTX helpers ----------------------------------
__device__ __forceinline__ uint32_t smem_u32(const void* p) {
    uint32_t a;
    asm("{ .reg .u64 t; cvta.to.shared.u64 t, %1; cvt.u32.u64 %0, t; }"
        : "=r"(a) : "l"(p));
    return a;
}
__device__ __forceinline__ void cp16(uint32_t saddr, const void* g) {
    asm volatile("cp.async.cg.shared.global [%0], [%1], 16;" :: "r"(saddr), "l"(g));
}
__device__ __forceinline__ void cp_commit() { asm volatile("cp.async.commit_group;" ::: "memory"); }
template <int N> __device__ __forceinline__ void cp_wait() {
    asm volatile("cp.async.wait_group %0;" :: "n"(N) : "memory");
}
__device__ __forceinline__ void ldm_x4(uint32_t* r, uint32_t addr) {
    asm volatile("ldmatrix.sync.aligned.m8n8.x4.shared.b16 {%0,%1,%2,%3}, [%4];"
        : "=r"(r[0]), "=r"(r[1]), "=r"(r[2]), "=r"(r[3]) : "r"(addr));
}
__device__ __forceinline__ void ldm_x4_t(uint32_t* r, uint32_t addr) {
    asm volatile("ldmatrix.sync.aligned.m8n8.x4.trans.shared.b16 {%0,%1,%2,%3}, [%4];"
        : "=r"(r[0]), "=r"(r[1]), "=r"(r[2]), "=r"(r[3]) : "r"(addr));
}
// fp16 MMA, fp32 accum
__device__ __forceinline__ void mma16816h(float* d, const uint32_t* a, const uint32_t* b) {
    asm volatile(
        "mma.sync.aligned.m16n8k16.row.col.f32.f16.f16.f32 "
        "{%0,%1,%2,%3}, {%4,%5,%6,%7}, {%8,%9}, {%0,%1,%2,%3};"
        : "+f"(d[0]), "+f"(d[1]), "+f"(d[2]), "+f"(d[3])
        : "r"(a[0]), "r"(a[1]), "r"(a[2]), "r"(a[3]), "r"(b[0]), "r"(b[1]));
}
__device__ __forceinline__ uint32_t pack_f16(float lo, float hi) {
    __half2 h = __floats2half2_rn(lo, hi);
    return *(uint32_t*)&h;
}

// ---------------------------------------------------------------------------
// Warp-MMA GEMM: C[M,N] = A[M,768] @ B[N,768]^T (+ bias), plain fp16.
// BM=BN=128, BK=64 (12 chunks), 8 warps (2x4), warp tile 64x32,
// 3-stage cp.async, single __syncthreads per chunk.
// Row stride 144 B: multiples mod 128 cover all eight 16B groups ->
// conflict-free ldmatrix.
// ---------------------------------------------------------------------------
#define GBM 128
#define GBN 128
#define GBK 64
#define GNCH (768 / GBK)          // 12
#define ROWBT 144                 // 64 halves + 16B pad
#define TILE  (128u * ROWBT)      // 18432
#define B_OFF TILE
#define STG   (2u * TILE)         // 36864
#define GEMM_SMEM (3 * 36864)     // 110592

__device__ __forceinline__ void gemm_load_chunk(
    uint32_t buf,
    const __half* __restrict__ A, const __half* __restrict__ B,
    int rowBase, int colBase, int k0, int tid)
{
#pragma unroll
    for (int it = 0; it < 4; it++) {
        int t = tid + it * 256;           // 0..1023
        int r = t >> 3, c = t & 7;        // row 0..127, 16B unit 0..7
        uint32_t soff = (uint32_t)(r * ROWBT + c * 16);
        size_t ga = (size_t)(rowBase + r) * 768 + k0 + c * 8;
        size_t gb = (size_t)(colBase + r) * 768 + k0 + c * 8;
        cp16(buf + soff, A + ga);
        cp16(buf + B_OFF + soff, B + gb);
    }
    cp_commit();
}

template <bool HALF_OUT>
__global__ void __launch_bounds__(256)
wmma_gemm(const __half* __restrict__ A, const __half* __restrict__ B,
          const float* __restrict__ bias, void* __restrict__ Cv, int N)
{
    const uint32_t sb = smem_u32(smem_raw);
    const int tid   = threadIdx.x;
    const int lane  = tid & 31;
    const int wid   = tid >> 5;
    const int warpM = wid >> 2;
    const int warpN = wid & 3;
    const int rowBase = blockIdx.y * GBM;
    const int colBase = blockIdx.x * GBN;

    float acc[4][4][4];
#pragma unroll
    for (int i = 0; i < 4; i++)
#pragma unroll
        for (int j = 0; j < 4; j++)
#pragma unroll
            for (int e = 0; e < 4; e++) acc[i][j][e] = 0.f;

    const uint32_t a_lane = (uint32_t)((warpM * 64 + (lane & 15)) * ROWBT + (lane >> 4) * 16);
    const uint32_t b_lane = B_OFF
        + (uint32_t)((warpN * 32 + ((lane & 7) | ((lane >> 4) << 3))) * ROWBT
                     + ((lane >> 3) & 1) * 16);

    gemm_load_chunk(sb,       A, B, rowBase, colBase, 0,   tid);
    gemm_load_chunk(sb + STG, A, B, rowBase, colBase, GBK, tid);

    for (int ch = 0; ch < GNCH; ch++) {
        if (ch < GNCH - 1) cp_wait<1>(); else cp_wait<0>();
        __syncthreads();
        // safe: sync proves all warps finished compute(ch-1), the last
        // consumer of buffer (ch+2)%3.
        if (ch + 2 < GNCH)
            gemm_load_chunk(sb + (uint32_t)((ch + 2) % 3) * STG,
                            A, B, rowBase, colBase, (ch + 2) * GBK, tid);
        const uint32_t buf = sb + (uint32_t)(ch % 3) * STG;

#pragma unroll
        for (int k16 = 0; k16 < 4; k16++) {
            const uint32_t kb = (uint32_t)(k16 * 32);
            uint32_t ah[4][4];
#pragma unroll
            for (int mt = 0; mt < 4; mt++)
                ldm_x4(ah[mt], buf + a_lane + kb + (uint32_t)(mt * 16 * ROWBT));
            uint32_t bh[2][4];
#pragma unroll
            for (int half = 0; half < 2; half++)
                ldm_x4(bh[half], buf + b_lane + kb + (uint32_t)(half * 16 * ROWBT));
#pragma unroll
            for (int mt = 0; mt < 4; mt++)
#pragma unroll
                for (int nt = 0; nt < 4; nt++)
                    mma16816h(acc[mt][nt], ah[mt], &bh[nt >> 1][(nt & 1) * 2]);
        }
    }

#pragma unroll
    for (int mt = 0; mt < 4; mt++) {
        const int row0 = rowBase + warpM * 64 + mt * 16 + (lane >> 2);
#pragma unroll
        for (int nt = 0; nt < 4; nt++) {
            const int col = colBase + warpN * 32 + nt * 8 + (lane & 3) * 2;
            float b0 = 0.f, b1 = 0.f;
            if (bias != nullptr) { b0 = bias[col]; b1 = bias[col + 1]; }
            if (HALF_OUT) {
                __half* Ch = (__half*)Cv;
                *(__half2*)&Ch[(size_t)row0 * N + col] =
                    __floats2half2_rn(acc[mt][nt][0] + b0, acc[mt][nt][1] + b1);
                *(__half2*)&Ch[(size_t)(row0 + 8) * N + col] =
                    __floats2half2_rn(acc[mt][nt][2] + b0, acc[mt][nt][3] + b1);
            } else {
                float* C = (float*)Cv;
                *(float2*)&C[(size_t)row0 * N + col] =
                    make_float2(acc[mt][nt][0] + b0, acc[mt][nt][1] + b1);
                *(float2*)&C[(size_t)(row0 + 8) * N + col] =
                    make_float2(acc[mt][nt][2] + b0, acc[mt][nt][3] + b1);
            }
        }
    }
}

// ---------------------------------------------------------------------------
// fp32 -> fp16 round (for x)
// ---------------------------------------------------------------------------
__global__ void round_fp32(const float* __restrict__ src,
                           __half* __restrict__ hi, size_t n4)
{
    size_t i = (size_t)blockIdx.x * blockDim.x + threadIdx.x;
    if (i >= n4) return;
    float4 v = ((const float4*)src)[i];
    __half2* hp = (__half2*)hi;
    hp[i * 2 + 0] = __halves2half2(__float2half(v.x), __float2half(v.y));
    hp[i * 2 + 1] = __halves2half2(__float2half(v.z), __float2half(v.w));
}

// ---------------------------------------------------------------------------
// W [K,N] row-major -> [N,K] K-major fp16 (transpose + round)
// ---------------------------------------------------------------------------
__global__ void transpose_round(const float* __restrict__ W,
                                __half* __restrict__ hi, int K, int N)
{
    __shared__ float t[32][33];
    int n0 = blockIdx.x * 32, k0 = blockIdx.y * 32;
    for (int r = threadIdx.y; r < 32; r += 8)
        t[r][threadIdx.x] = W[(size_t)(k0 + r) * N + n0 + threadIdx.x];
    __syncthreads();
    for (int r = threadIdx.y; r < 32; r += 8) {
        float v = t[threadIdx.x][r];
        hi[(size_t)(n0 + r) * K + k0 + threadIdx.x] = __float2half(v);
    }
}

// ---------------------------------------------------------------------------
// Fused MMA attention, all fp16 (R9). Grid (LWIN, NHEADS, B), 13 warps.
// Epilogue emits fp16 att (hi only — stage 3 is now 1-term).
// ---------------------------------------------------------------------------
#define AROW   144
#define SQ_O   0
#define SK_O   29952
#define SV_O   59904
#define ATT_SMEM 89856
#define ATT_THREADS 416

__global__ void __launch_bounds__(ATT_THREADS)
win_attn_mma()
{
    const uint32_t sb = smem_u32(smem_raw);
    const int l    = blockIdx.x;
    const int head = blockIdx.y;
    const int b    = blockIdx.z;
    const int wy   = l / NW_WIN;
    const int wx   = l % NW_WIN;
    const int tid  = threadIdx.x;
    const int lane = tid & 31;
    const int w    = tid >> 5;       // 0..12

    // ---- stage Q,K,V (fp16) into smem; zero-fill pad rows ----
#pragma unroll
    for (int it = 0; it < 12; it++) {
        int idx = tid + it * ATT_THREADS;   // 0..4991
        int arr = idx / 1664;               // 0=Q 1=K 2=V
        int rem = idx - arr * 1664;
        int row = rem >> 3;                 // 0..207
        int c   = rem & 7;                  // 16B unit
        uint32_t soff = (uint32_t)(arr * SK_O + row * AROW + c * 16);
        int rr = row / WIN, cc = row % WIN;
        int hh = wy * WIN + rr, ww = wx * WIN + cc;
        if (row < NWTOK && hh < H_IMG && ww < W_IMG) {
            size_t gbase = ((size_t)(b * NTOK + hh * W_IMG + ww)) * QKV_DIM
                           + (size_t)head * HDIM + (size_t)arr * C_DIM + c * 8;
            cp16(sb + soff, g_qkvh + gbase);
        } else {
            *(uint4*)(smem_raw + soff) = make_uint4(0, 0, 0, 0);
        }
    }
    cp_commit();
    cp_wait<0>();
    __syncthreads();

    const uint32_t a_lane  = sb + SQ_O
        + (uint32_t)((w * 16 + (lane & 15)) * AROW + (lane >> 4) * 16);
    const uint32_t kb_lane = sb + SK_O
        + (uint32_t)((((lane & 7) | ((lane >> 4) << 3))) * AROW + ((lane >> 3) & 1) * 16);
    const uint32_t vb_lane = sb + SV_O
        + (uint32_t)(((((lane >> 3) & 1) * 8 + (lane & 7))) * AROW + (lane >> 4) * 16);

    uint32_t qa[4][4];
#pragma unroll
    for (int kt = 0; kt < 4; kt++) ldm_x4(qa[kt], a_lane + kt * 32);

    const int cq = 2 * (lane & 3);

    // ---- pass 1: row max ----
    float m0 = -1e30f, m1 = -1e30f;
    for (int t = 0; t < 13; t++) {
        float s0[4] = {0.f, 0.f, 0.f, 0.f}, s1[4] = {0.f, 0.f, 0.f, 0.f};
#pragma unroll
        for (int kt = 0; kt < 4; kt++) {
            uint32_t kb[4];
            ldm_x4(kb, kb_lane + (uint32_t)(t * 16 * AROW + kt * 32));
            mma16816h(s0, qa[kt], &kb[0]);
            mma16816h(s1, qa[kt], &kb[2]);
        }
        int j0 = t * 16 + cq;
        int j1 = j0 + 8;
        if (j0     < NWTOK) { m0 = fmaxf(m0, s0[0]); m1 = fmaxf(m1, s0[2]); }
        if (j0 + 1 < NWTOK) { m0 = fmaxf(m0, s0[1]); m1 = fmaxf(m1, s0[3]); }
        if (j1     < NWTOK) { m0 = fmaxf(m0, s1[0]); m1 = fmaxf(m1, s1[2]); }
        if (j1 + 1 < NWTOK) { m0 = fmaxf(m0, s1[1]); m1 = fmaxf(m1, s1[3]); }
    }
    m0 *= 0.125f;  m1 *= 0.125f;
#pragma unroll
    for (int off = 1; off <= 2; off <<= 1) {
        m0 = fmaxf(m0, __shfl_xor_sync(0xffffffffu, m0, off));
        m1 = fmaxf(m1, __shfl_xor_sync(0xffffffffu, m1, off));
    }

    // ---- pass 2: recompute S, P = exp(s*0.125 - m), O += P@V ----
    float o[8][4];
#pragma unroll
    for (int i = 0; i < 8; i++)
#pragma unroll
        for (int e = 0; e < 4; e++) o[i][e] = 0.f;
    float sum0 = 0.f, sum1 = 0.f;

    for (int t = 0; t < 13; t++) {
        float s0[4] = {0.f, 0.f, 0.f, 0.f}, s1[4] = {0.f, 0.f, 0.f, 0.f};
#pragma unroll
        for (int kt = 0; kt < 4; kt++) {
            uint32_t kb[4];
            ldm_x4(kb, kb_lane + (uint32_t)(t * 16 * AROW + kt * 32));
            mma16816h(s0, qa[kt], &kb[0]);
            mma16816h(s1, qa[kt], &kb[2]);
        }
        int j0 = t * 16 + cq;
        int j1 = j0 + 8;
        float p0 = (j0     < NWTOK) ? __expf(s0[0] * 0.125f - m0) : 0.f;
        float p1 = (j0 + 1 < NWTOK) ? __expf(s0[1] * 0.125f - m0) : 0.f;
        float p2 = (j0     < NWTOK) ? __expf(s0[2] * 0.125f - m1) : 0.f;
        float p3 = (j0 + 1 < NWTOK) ? __expf(s0[3] * 0.125f - m1) : 0.f;
        float u0 = (j1     < NWTOK) ? __expf(s1[0] * 0.125f - m0) : 0.f;
        float u1 = (j1 + 1 < NWTOK) ? __expf(s1[1] * 0.125f - m0) : 0.f;
        float u2 = (j1     < NWTOK) ? __expf(s1[2] * 0.125f - m1) : 0.f;
        float u3 = (j1 + 1 < NWTOK) ? __expf(s1[3] * 0.125f - m1) : 0.f;
        sum0 += p0 + p1 + u0 + u1;
        sum1 += p2 + p3 + u2 + u3;

        uint32_t pah[4], pal[4];
        pah[0] = pack_f16(p0, p1);  pah[1] = pack_f16(p2, p3);
        pah[2] = pack_f16(u0, u1);  pah[3] = pack_f16(u2, u3);
        {
            float q0 = __half2float(__low2half(*(__half2*)&pah[0]));
            float q1 = __half2float(__high2half(*(__half2*)&pah[0]));
            float q2 = __half2float(__low2half(*(__half2*)&pah[1]));
            float q3 = __half2float(__high2half(*(__half2*)&pah[1]));
            float r0 = __half2float(__low2half(*(__half2*)&pah[2]));
            float r1 = __half2float(__high2half(*(__half2*)&pah[2]));
            float r2 = __half2float(__low2half(*(__half2*)&pah[3]));
            float r3 = __half2float(__high2half(*(__half2*)&pah[3]));
            pal[0] = pack_f16(p0 - q0, p1 - q1);
            pal[1] = pack_f16(p2 - q2, p3 - q3);
            pal[2] = pack_f16(u0 - r0, u1 - r1);
            pal[3] = pack_f16(u2 - r2, u3 - r3);
        }

#pragma unroll
        for (int dg = 0; dg < 4; dg++) {
            uint32_t vb[4];
            ldm_x4_t(vb, vb_lane + (uint32_t)(t * 16 * AROW + dg * 32));
            mma16816h(o[dg * 2 + 0], pah, &vb[0]);
            mma16816h(o[dg * 2 + 0], pal, &vb[0]);
            mma16816h(o[dg * 2 + 1], pah, &vb[2]);
            mma16816h(o[dg * 2 + 1], pal, &vb[2]);
        }
    }
#pragma unroll
    for (int off = 1; off <= 2; off <<= 1) {
        sum0 += __shfl_xor_sync(0xffffffffu, sum0, off);
        sum1 += __shfl_xor_sync(0xffffffffu, sum1, off);
    }
    const float inv0 = 1.f / sum0;
    const float inv1 = 1.f / sum1;

    // ---- epilogue: O/sum -> g_atthi (fp16) ----
    const int r0 = w * 16 + (lane >> 2);
#pragma unroll
    for (int half = 0; half < 2; half++) {
        const int row = r0 + half * 8;
        if (row >= NWTOK) continue;
        const int rr = row / WIN, cc = row % WIN;
        const int hh = wy * WIN + rr, ww = wx * WIN + cc;
        if (hh >= H_IMG || ww >= W_IMG) continue;
        const float inv = half ? inv1 : inv0;
        const size_t obase = ((size_t)(b * NTOK + hh * W_IMG + ww)) * C_DIM
                             + (size_t)head * HDIM;
#pragma unroll
        for (int dt = 0; dt < 8; dt++) {
            const int col = dt * 8 + cq;
            *(__half2*)&g_atthi[obase + col] = __floats2half2_rn(
                o[dt][half * 2 + 0] * inv, o[dt][half * 2 + 1] * inv);
        }
    }
}

// ---------------------------------------------------------------------------
// Launch
// ---------------------------------------------------------------------------
extern "C" void kernel_launch(void* const* d_in, const int* in_sizes, int n_in,
                              void* d_out, int out_size)
{
    const float* x     = (const float*)d_in[0];
    const float* Wqkv  = (const float*)d_in[1];
    const float* Wproj = (const float*)d_in[2];
    const float* bproj = (const float*)d_in[3];
    float* out = (float*)d_out;

    __half *qkvh, *xhi, *wqh, *wph, *athi;
    cudaGetSymbolAddress((void**)&qkvh, g_qkvh);
    cudaGetSymbolAddress((void**)&xhi,  g_xhi);
    cudaGetSymbolAddress((void**)&wqh,  g_wqkv_hi);
    cudaGetSymbolAddress((void**)&wph,  g_wproj_hi);
    cudaGetSymbolAddress((void**)&athi, g_atthi);

    // convert x + weights to fp16
    {
        size_t n4 = (size_t)MTOT * C_DIM / 4;
        round_fp32<<<(unsigned)((n4 + 255) / 256), 256>>>(x, xhi, n4);
        transpose_round<<<dim3(QKV_DIM / 32, C_DIM / 32), dim3(32, 8)>>>(Wqkv, wqh, C_DIM, QKV_DIM);
        transpose_round<<<dim3(C_DIM / 32,  C_DIM / 32), dim3(32, 8)>>>(Wproj, wph, C_DIM, C_DIM);
    }

    cudaFuncSetAttribute((const void*)wmma_gemm<true>,
                         cudaFuncAttributeMaxDynamicSharedMemorySize, GEMM_SMEM);
    cudaFuncSetAttribute((const void*)wmma_gemm<false>,
                         cudaFuncAttributeMaxDynamicSharedMemorySize, GEMM_SMEM);
    cudaFuncSetAttribute((const void*)win_attn_mma,
                         cudaFuncAttributeMaxDynamicSharedMemorySize, ATT_SMEM);

    // Stage 1: qkv(fp16) = x @ Wqkv
    wmma_gemm<true><<<dim3(QKV_DIM / GBN, MTOT / GBM), 256, GEMM_SMEM>>>(
        xhi, wqh, nullptr, (void*)qkvh, QKV_DIM);

    // Stage 2: fused all-fp16 MMA attention
    win_attn_mma<<<dim3(LWIN, NHEADS, B_SZ), ATT_THREADS, ATT_SMEM>>>();

    // Stage 3: out = att @ Wproj + bproj (plain fp16, fp32 out)
    wmma_gemm<false><<<dim3(C_DIM / GBN, MTOT / GBM), 256, GEMM_SMEM>>>(
        athi, wph, bproj, (void*)out, C_DIM);
}